// round 4
// baseline (speedup 1.0000x reference)
#include <cuda_runtime.h>
#include <math.h>
#include <stdint.h>

// Problem dims (fixed by reference)
#define Bdim 4
#define Sdim 2048
#define Edim 1024
#define Hdim 16
#define DKdim 64
#define FFNdim 4096
#define NQdim 8
#define NTOK (Bdim * Sdim)
#define EPSv 1e-5f

// Scratch (alloc-free rule: __device__ globals)
__device__ float g_attn[(size_t)NTOK * Edim];    // 33.5 MB
__device__ float g_h[(size_t)NTOK * Edim];       // 33.5 MB
__device__ float g_qout[NTOK * NQdim];           // 256 KB
__device__ float g_w2t[(size_t)Edim * FFNdim];   // 16.8 MB (tf32-rounded)
__device__ float g_xh[(size_t)NTOK * Edim];      // 33.5 MB (tf32 hi part of x)
__device__ float g_xl[(size_t)NTOK * Edim];      // 33.5 MB (tf32 lo part of x)

// ---------------------------------------------------------------------------
// Helpers
// ---------------------------------------------------------------------------
__device__ __forceinline__ uint32_t smem_u32(const void* p) {
    uint32_t a;
    asm("{ .reg .u64 t; cvta.to.shared.u64 t, %1; cvt.u32.u64 %0, t; }"
        : "=r"(a) : "l"(p));
    return a;
}
__device__ __forceinline__ float cvt_tf32(float v) {
    uint32_t t;
    asm("cvt.rna.tf32.f32 %0, %1;" : "=r"(t) : "f"(v));
    return __uint_as_float(t);
}
__device__ __forceinline__ uint32_t cvt_tf32_u(float v) {
    uint32_t t;
    asm("cvt.rna.tf32.f32 %0, %1;" : "=r"(t) : "f"(v));
    return t;
}
__device__ __forceinline__ void mma_tf32(float c[4], const uint32_t a[4],
                                         const uint32_t b[2]) {
    asm volatile(
        "mma.sync.aligned.m16n8k8.row.col.f32.tf32.tf32.f32 "
        "{%0,%1,%2,%3}, {%4,%5,%6,%7}, {%8,%9}, {%0,%1,%2,%3};"
        : "+f"(c[0]), "+f"(c[1]), "+f"(c[2]), "+f"(c[3])
        : "r"(a[0]), "r"(a[1]), "r"(a[2]), "r"(a[3]), "r"(b[0]), "r"(b[1]));
}
__device__ __forceinline__ void cp16(uint32_t dst, const void* src) {
    asm volatile("cp.async.ca.shared.global [%0], [%1], 16;" :: "r"(dst), "l"(src));
}
__device__ __forceinline__ void cp_commit() {
    asm volatile("cp.async.commit_group;" ::: "memory");
}
template <int N>
__device__ __forceinline__ void cp_wait() {
    asm volatile("cp.async.wait_group %0;" :: "n"(N) : "memory");
}

// ---------------------------------------------------------------------------
// x -> (xh, xl): tf32 split for 3xTF32 score GEMM
// ---------------------------------------------------------------------------
__global__ void __launch_bounds__(256) cvt_x_kernel(const float* __restrict__ x,
                                                    float* __restrict__ xh,
                                                    float* __restrict__ xl) {
    size_t i = ((size_t)blockIdx.x * 256 + threadIdx.x) * 4;
    float4 v = *(const float4*)(x + i);
    float4 hpart, lpart;
    hpart.x = cvt_tf32(v.x); lpart.x = cvt_tf32(v.x - hpart.x);
    hpart.y = cvt_tf32(v.y); lpart.y = cvt_tf32(v.y - hpart.y);
    hpart.z = cvt_tf32(v.z); lpart.z = cvt_tf32(v.z - hpart.z);
    hpart.w = cvt_tf32(v.w); lpart.w = cvt_tf32(v.w - hpart.w);
    *(float4*)(xh + i) = hpart;
    *(float4*)(xl + i) = lpart;
}

// ---------------------------------------------------------------------------
// w2 -> tf32-rounded copy
// ---------------------------------------------------------------------------
__global__ void __launch_bounds__(256) cvt_w2_kernel(const float* __restrict__ w2,
                                                     float* __restrict__ w2t) {
    size_t i = ((size_t)blockIdx.x * 256 + threadIdx.x) * 4;
    float4 v = *(const float4*)(w2 + i);
    float4 o;
    o.x = cvt_tf32(v.x); o.y = cvt_tf32(v.y);
    o.z = cvt_tf32(v.z); o.w = cvt_tf32(v.w);
    *(float4*)(w2t + i) = o;
}

// ---------------------------------------------------------------------------
// Attention with mma.sync tf32. Per block: one (b,h), 128-query tile.
// 256 threads = 8 warps in 4x2 grid of 32x32 warp tiles.
// GEMM1 (scores) uses 3xTF32 split (hi/lo). K tiles double-buffered cp.async.
// Unnormalized streaming softmax (scores <= ~15, fp32-safe).
// ---------------------------------------------------------------------------
#define ASTR 68   // smem row stride in floats (68 % 32 == 4 -> conflict-free frags)
#define QT 128
#define KT 64
#define NKT (Sdim / KT)
// smem floats: Qh/Ql [128*ASTR] each, Kh/Kl [2 bufs][64*ASTR] each, Ps [128*ASTR]
#define ATTN_SMEM ((2 * QT * ASTR + 4 * KT * ASTR + QT * ASTR) * 4)  // 174080 B

__global__ void __launch_bounds__(256) attn_kernel(const float* __restrict__ xh,
                                                   const float* __restrict__ xl,
                                                   float* __restrict__ attn) {
    extern __shared__ float sm[];
    float* Qh  = sm;
    float* Ql  = Qh + QT * ASTR;
    float* Kh0 = Ql + QT * ASTR;            // [2][KT*ASTR]
    float* Kl0 = Kh0 + 2 * KT * ASTR;       // [2][KT*ASTR]
    float* Ps  = Kl0 + 2 * KT * ASTR;
    __shared__ float lred[QT][2];

    const int bh = blockIdx.y, b = bh >> 4, h = bh & 15;
    const int q0 = blockIdx.x << 7;
    const int tid = threadIdx.x, lane = tid & 31, w = tid >> 5;
    const int mw = w >> 1, nw = w & 1;
    const int RM = mw * 32, CN = nw * 32;
    const int r0 = lane >> 2, c0 = lane & 3;

    const size_t xbase = (size_t)b * Sdim * Edim + h * DKdim;
    const float* xhb = xh + xbase;
    const float* xlb = xl + xbase;

    const uint32_t sQh = smem_u32(Qh), sQl = smem_u32(Ql);
    const uint32_t sKh = smem_u32(Kh0), sKl = smem_u32(Kl0);

    // Load Q tile (hi+lo): 128 rows x 16 16B-chunks
#pragma unroll
    for (int i = 0; i < 8; i++) {
        int idx = tid + i * 256;
        int r = idx >> 4, ch = idx & 15;
        uint32_t off = (uint32_t)(r * ASTR * 4 + ch * 16);
        size_t g = (size_t)(q0 + r) * Edim + ch * 4;
        cp16(sQh + off, xhb + g);
        cp16(sQl + off, xlb + g);
    }
    cp_commit();

    // K tile loader: 64 rows x 16 chunks (hi+lo) into buffer bf
    auto load_k = [&](int bf, int kt) {
        uint32_t bo = (uint32_t)(bf * KT * ASTR * 4);
#pragma unroll
        for (int i = 0; i < 4; i++) {
            int idx = tid + i * 256;
            int r = idx >> 4, ch = idx & 15;
            uint32_t off = bo + (uint32_t)(r * ASTR * 4 + ch * 16);
            size_t g = (size_t)(kt * KT + r) * Edim + ch * 4;
            cp16(sKh + off, xhb + g);
            cp16(sKl + off, xlb + g);
        }
        cp_commit();
    };
    load_k(0, 0);

    float o[2][4][4] = {};
    float lsum[2][2] = {};

#pragma unroll 1
    for (int kt = 0; kt < NKT; kt++) {
        const int bf = kt & 1;
        if (kt + 1 < NKT) {
            load_k(bf ^ 1, kt + 1);
            cp_wait<1>();
        } else {
            cp_wait<0>();
        }
        __syncthreads();   // K tile bf (and Q on first iter) visible

        const float* Khb = Kh0 + bf * KT * ASTR;
        const float* Klb = Kl0 + bf * KT * ASTR;

        // ---- GEMM1: S = Q K^T (3xTF32 split), S tile 128x64 ----
        float s[2][4][4] = {};
#pragma unroll
        for (int ks = 0; ks < 8; ks++) {
            const int kk = ks * 8 + c0;
            uint32_t ah[2][4], al[2][4];
#pragma unroll
            for (int mt = 0; mt < 2; mt++) {
                int rr = RM + mt * 16 + r0;
                ah[mt][0] = __float_as_uint(Qh[rr * ASTR + kk]);
                ah[mt][1] = __float_as_uint(Qh[(rr + 8) * ASTR + kk]);
                ah[mt][2] = __float_as_uint(Qh[rr * ASTR + kk + 4]);
                ah[mt][3] = __float_as_uint(Qh[(rr + 8) * ASTR + kk + 4]);
                al[mt][0] = __float_as_uint(Ql[rr * ASTR + kk]);
                al[mt][1] = __float_as_uint(Ql[(rr + 8) * ASTR + kk]);
                al[mt][2] = __float_as_uint(Ql[rr * ASTR + kk + 4]);
                al[mt][3] = __float_as_uint(Ql[(rr + 8) * ASTR + kk + 4]);
            }
#pragma unroll
            for (int nt = 0; nt < 4; nt++) {
                int nn = CN + nt * 8 + r0;
                uint32_t bhf[2], blf[2];
                bhf[0] = __float_as_uint(Khb[nn * ASTR + kk]);
                bhf[1] = __float_as_uint(Khb[nn * ASTR + kk + 4]);
                blf[0] = __float_as_uint(Klb[nn * ASTR + kk]);
                blf[1] = __float_as_uint(Klb[nn * ASTR + kk + 4]);
#pragma unroll
                for (int mt = 0; mt < 2; mt++) {
                    mma_tf32(s[mt][nt], ah[mt], bhf);
                    mma_tf32(s[mt][nt], ah[mt], blf);
                    mma_tf32(s[mt][nt], al[mt], bhf);
                }
            }
        }

        // ---- exp + stage P (tf32) + row-sum accumulate ----
#pragma unroll
        for (int mt = 0; mt < 2; mt++)
#pragma unroll
            for (int nt = 0; nt < 4; nt++)
#pragma unroll
                for (int j = 0; j < 4; j++) {
                    int rr = RM + mt * 16 + r0 + (j >> 1) * 8;
                    int cc = CN + nt * 8 + c0 * 2 + (j & 1);
                    float p = __expf(s[mt][nt][j] * 0.125f);
                    lsum[mt][j >> 1] += p;
                    Ps[rr * ASTR + cc] = cvt_tf32(p);
                }
        __syncthreads();  // P cols cross warp boundaries

        // ---- GEMM2: O += P V  (V = K tile hi part) ----
#pragma unroll
        for (int ks = 0; ks < 8; ks++) {
            const int kk = ks * 8 + c0;
            uint32_t a[2][4];
#pragma unroll
            for (int mt = 0; mt < 2; mt++) {
                int rr = RM + mt * 16 + r0;
                a[mt][0] = __float_as_uint(Ps[rr * ASTR + kk]);
                a[mt][1] = __float_as_uint(Ps[(rr + 8) * ASTR + kk]);
                a[mt][2] = __float_as_uint(Ps[rr * ASTR + kk + 4]);
                a[mt][3] = __float_as_uint(Ps[(rr + 8) * ASTR + kk + 4]);
            }
#pragma unroll
            for (int nt = 0; nt < 4; nt++) {
                int nn = CN + nt * 8 + r0;
                uint32_t bb[2];
                bb[0] = __float_as_uint(Khb[kk * ASTR + nn]);
                bb[1] = __float_as_uint(Khb[(kk + 4) * ASTR + nn]);
                mma_tf32(o[0][nt], a[0], bb);
                mma_tf32(o[1][nt], a[1], bb);
            }
        }
        __syncthreads();  // K buf + Ps fully consumed before reuse
    }

    // ---- final row-sum reduce ----
#pragma unroll
    for (int mt = 0; mt < 2; mt++)
#pragma unroll
        for (int hh = 0; hh < 2; hh++) {
            float v = lsum[mt][hh];
            v += __shfl_xor_sync(0xffffffffu, v, 1);
            v += __shfl_xor_sync(0xffffffffu, v, 2);
            lsum[mt][hh] = v;
        }
    if (c0 == 0) {
#pragma unroll
        for (int mt = 0; mt < 2; mt++)
#pragma unroll
            for (int hh = 0; hh < 2; hh++)
                lred[RM + mt * 16 + r0 + hh * 8][nw] = lsum[mt][hh];
    }
    __syncthreads();

    float* ob = attn + ((size_t)b * Sdim + q0) * Edim + h * DKdim;
#pragma unroll
    for (int mt = 0; mt < 2; mt++)
#pragma unroll
        for (int hh = 0; hh < 2; hh++) {
            int rr = RM + mt * 16 + r0 + hh * 8;
            float linv = 1.0f / (lred[rr][0] + lred[rr][1]);
#pragma unroll
            for (int nt = 0; nt < 4; nt++) {
                float2 v;
                v.x = o[mt][nt][hh * 2] * linv;
                v.y = o[mt][nt][hh * 2 + 1] * linv;
                *(float2*)(ob + (size_t)rr * Edim + CN + nt * 8 + c0 * 2) = v;
            }
        }
}

// ---------------------------------------------------------------------------
// Residual + LayerNorm (unchanged)
// ---------------------------------------------------------------------------
__global__ void __launch_bounds__(256) ln_kernel(const float* __restrict__ a,
                                                 const float* __restrict__ resid,
                                                 const float* __restrict__ gamma,
                                                 const float* __restrict__ beta,
                                                 float* __restrict__ out,
                                                 float* __restrict__ qout,
                                                 const float* __restrict__ theta) {
    const int t = blockIdx.x;
    const int tid = threadIdx.x;
    const float* pa = a + (size_t)t * Edim;
    const float* pr = resid ? resid + (size_t)t * Edim : nullptr;

    float v[4];
    float s = 0.0f, s2 = 0.0f;
#pragma unroll
    for (int i = 0; i < 4; i++) {
        int e = tid + i * 256;
        float val = pa[e];
        if (pr) val += pr[e];
        v[i] = val;
        s += val;
        s2 += val * val;
    }
#pragma unroll
    for (int off = 16; off > 0; off >>= 1) {
        s  += __shfl_down_sync(0xffffffffu, s, off);
        s2 += __shfl_down_sync(0xffffffffu, s2, off);
    }
    __shared__ float r1[8], r2[8], stat[2];
    const int warp = tid >> 5, lane = tid & 31;
    if (lane == 0) { r1[warp] = s; r2[warp] = s2; }
    __syncthreads();
    if (tid == 0) {
        float S1 = 0.0f, S2 = 0.0f;
#pragma unroll
        for (int wi = 0; wi < 8; wi++) { S1 += r1[wi]; S2 += r2[wi]; }
        float mu = S1 * (1.0f / Edim);
        float var = S2 * (1.0f / Edim) - mu * mu;
        stat[0] = mu;
        stat[1] = rsqrtf(var + EPSv);
    }
    __syncthreads();
    const float mu = stat[0], rs = stat[1];

    float* po = out + (size_t)t * Edim;
#pragma unroll
    for (int i = 0; i < 4; i++) {
        int e = tid + i * 256;
        po[e] = (v[i] - mu) * rs * gamma[e] + beta[e];
    }
    if (qout != nullptr && tid < NQdim) {
        float hv = (v[0] - mu) * rs * gamma[tid] + beta[tid];
        qout[t * NQdim + tid] = cosf(hv) * cosf(theta[tid]);
    }
}

// ---------------------------------------------------------------------------
// Fused FFN: out = h + relu(qout @ w1^T + b1) @ w2t^T + b2
// The hid tile (128 tokens x 64 f per chunk) is computed IN-KERNEL via a
// rank-8 mma from register-resident qout fragments + staged w1 chunk, then
// STS'd into the A smem tile. No hid tensor in global memory.
// CTA: 128 tokens x 128 e, 256 threads = 8 warps (32x64 GEMM2 warp tiles).
// K chunks of 64, w2t/w1/b1 double-buffered cp.async.
// ---------------------------------------------------------------------------
#define FK 64
#define NFCH (FFNdim / FK)   // 64
// smem floats: A [128*ASTR], B [2][128*ASTR], w1s [2][64*8], b1s [2][64]
#define FFN_SMEM ((QT * ASTR + 2 * QT * ASTR + 2 * FK * 8 + 2 * FK) * 4)  // 108992 B

__global__ void __launch_bounds__(256) ffn_fused(const float* __restrict__ qout,
                                                 const float* __restrict__ w1,
                                                 const float* __restrict__ b1,
                                                 const float* __restrict__ w2t,
                                                 const float* __restrict__ b2,
                                                 const float* __restrict__ hres,
                                                 float* __restrict__ out) {
    extern __shared__ float sm[];
    float* As  = sm;                       // [128][ASTR]
    float* Bs0 = As + QT * ASTR;           // [2][128][ASTR]
    float* w1s = Bs0 + 2 * QT * ASTR;      // [2][64*8]
    float* b1s = w1s + 2 * FK * 8;         // [2][64]

    const uint32_t sB = smem_u32(Bs0), sW1 = smem_u32(w1s), sB1 = smem_u32(b1s);
    const int tid = threadIdx.x, lane = tid & 31, w = tid >> 5;
    const int mw = w >> 1, nw = w & 1;
    const int RM = mw * 32, CN = nw * 64;
    const int r0 = lane >> 2, c0 = lane & 3;
    const int e0 = blockIdx.x * 128;
    const int t0 = blockIdx.y * 128;

    // qout A-fragments (tf32), constant across all chunks
    uint32_t aq[2][4];
#pragma unroll
    for (int mt = 0; mt < 2; mt++) {
#pragma unroll
        for (int j = 0; j < 4; j++) {
            int row = t0 + RM + mt * 16 + r0 + (j & 1) * 8;
            int col = c0 + (j >> 1) * 4;
            aq[mt][j] = cvt_tf32_u(qout[row * NQdim + col]);
        }
    }

    // chunk loader: w2t B-tile + w1 chunk + b1 chunk into buffer ls
    auto load_chunk = [&](int ls, int lc) {
        uint32_t Bb = sB + (uint32_t)(ls * QT * ASTR * 4);
#pragma unroll
        for (int i = 0; i < 8; i++) {
            int idx = tid + i * 256;
            int r = idx >> 4, ch = idx & 15;
            cp16(Bb + (uint32_t)(r * ASTR * 4 + ch * 16),
                 w2t + (size_t)(e0 + r) * FFNdim + lc * FK + ch * 4);
        }
        if (tid < 128) {   // w1 chunk: 64 rows x 8 floats = 128 x 16B
            int r = tid >> 1, ch = tid & 1;
            cp16(sW1 + (uint32_t)(ls * FK * 8 * 4 + (r * 8 + ch * 4) * 4),
                 w1 + (size_t)(lc * FK + r) * NQdim + ch * 4);
        } else if (tid < 144) {  // b1 chunk: 64 floats = 16 x 16B
            int i = tid - 128;
            cp16(sB1 + (uint32_t)(ls * FK * 4 + i * 16), b1 + lc * FK + i * 4);
        }
        cp_commit();
    };
    load_chunk(0, 0);

    float o[2][8][4] = {};

#pragma unroll 1
    for (int kc = 0; kc < NFCH; kc++) {
        const int s = kc & 1;
        if (kc + 1 < NFCH) {
            load_chunk(s ^ 1, kc + 1);
            cp_wait<1>();
        } else {
            cp_wait<0>();
        }
        __syncthreads();   // chunk kc staged

        // ---- build A tile: hid = relu(qout @ w1c^T + b1c), tf32 ----
        {
            const float* w1c = w1s + s * FK * 8;
            const float* b1c = b1s + s * FK;
#pragma unroll
            for (int nt2 = 0; nt2 < 4; nt2++) {
                const int f0 = nw * 32 + nt2 * 8;
                uint32_t bw[2];
                bw[0] = cvt_tf32_u(w1c[(f0 + r0) * 8 + c0]);
                bw[1] = cvt_tf32_u(w1c[(f0 + r0) * 8 + c0 + 4]);
                float bv0 = b1c[f0 + c0 * 2], bv1 = b1c[f0 + c0 * 2 + 1];
#pragma unroll
                for (int mt = 0; mt < 2; mt++) {
                    float c4[4] = {0.f, 0.f, 0.f, 0.f};
                    mma_tf32(c4, aq[mt], bw);
                    int row = RM + mt * 16 + r0;
                    float2 v0, v1;
                    v0.x = cvt_tf32(fmaxf(c4[0] + bv0, 0.0f));
                    v0.y = cvt_tf32(fmaxf(c4[1] + bv1, 0.0f));
                    v1.x = cvt_tf32(fmaxf(c4[2] + bv0, 0.0f));
                    v1.y = cvt_tf32(fmaxf(c4[3] + bv1, 0.0f));
                    *(float2*)(As + row * ASTR + f0 + c0 * 2) = v0;
                    *(float2*)(As + (row + 8) * ASTR + f0 + c0 * 2) = v1;
                }
            }
        }
        __syncthreads();   // A tile complete

        // ---- GEMM2 chunk: o += A (128xFK) @ B^T (128xFK) ----
        const float* Bsc = Bs0 + s * QT * ASTR;
#pragma unroll
        for (int ks = 0; ks < 8; ks++) {
            const int kk = ks * 8 + c0;
            uint32_t a[2][4];
#pragma unroll
            for (int mt = 0; mt < 2; mt++) {
                int rr = RM + mt * 16 + r0;
                a[mt][0] = __float_as_uint(As[rr * ASTR + kk]);
                a[mt][1] = __float_as_uint(As[(rr + 8) * ASTR + kk]);
                a[mt][2] = __float_as_uint(As[rr * ASTR + kk + 4]);
                a[mt][3] = __float_as_uint(As[(rr + 8) * ASTR + kk + 4]);
            }
#pragma unroll
            for (int nt = 0; nt < 8; nt++) {
                int nn = CN + nt * 8 + r0;
                uint32_t bb[2];
                bb[0] = __float_as_uint(Bsc[nn * ASTR + kk]);
                bb[1] = __float_as_uint(Bsc[nn * ASTR + kk + 4]);
                mma_tf32(o[0][nt], a[0], bb);
                mma_tf32(o[1][nt], a[1], bb);
            }
        }
        __syncthreads();   // A + B buf consumed before rewrite
    }

    // Epilogue: + b2 + residual h
#pragma unroll
    for (int mt = 0; mt < 2; mt++)
#pragma unroll
        for (int hh = 0; hh < 2; hh++) {
            int tt = t0 + RM + mt * 16 + r0 + hh * 8;
#pragma unroll
            for (int nt = 0; nt < 8; nt++) {
                int ee = e0 + CN + nt * 8 + c0 * 2;
                float2 hv = *(const float2*)(hres + (size_t)tt * Edim + ee);
                float2 bv = *(const float2*)(b2 + ee);
                float2 ov;
                ov.x = o[mt][nt][hh * 2] + hv.x + bv.x;
                ov.y = o[mt][nt][hh * 2 + 1] + hv.y + bv.y;
                *(float2*)(out + (size_t)tt * Edim + ee) = ov;
            }
        }
}

// ---------------------------------------------------------------------------
extern "C" void kernel_launch(void* const* d_in, const int* in_sizes, int n_in,
                              void* d_out, int out_size) {
    const float* x      = (const float*)d_in[0];
    const float* theta  = (const float*)d_in[1];
    const float* w1     = (const float*)d_in[2];
    const float* b1     = (const float*)d_in[3];
    const float* w2     = (const float*)d_in[4];
    const float* b2     = (const float*)d_in[5];
    const float* gamma1 = (const float*)d_in[6];
    const float* beta1  = (const float*)d_in[7];
    const float* gamma2 = (const float*)d_in[8];
    const float* beta2  = (const float*)d_in[9];
    float* out = (float*)d_out;

    float *attn_p, *h_p, *qout_p, *w2t_p, *xh_p, *xl_p;
    cudaGetSymbolAddress((void**)&attn_p, g_attn);
    cudaGetSymbolAddress((void**)&h_p, g_h);
    cudaGetSymbolAddress((void**)&qout_p, g_qout);
    cudaGetSymbolAddress((void**)&w2t_p, g_w2t);
    cudaGetSymbolAddress((void**)&xh_p, g_xh);
    cudaGetSymbolAddress((void**)&xl_p, g_xl);

    cudaFuncSetAttribute(attn_kernel, cudaFuncAttributeMaxDynamicSharedMemorySize,
                         ATTN_SMEM);
    cudaFuncSetAttribute(ffn_fused, cudaFuncAttributeMaxDynamicSharedMemorySize,
                         FFN_SMEM);

    // 0) precision prep
    cvt_w2_kernel<<<(Edim * FFNdim) / 1024, 256>>>(w2, w2t_p);
    cvt_x_kernel<<<((size_t)NTOK * Edim) / 1024, 256>>>(x, xh_p, xl_p);
    // 1) attention (tensor cores, 3xTF32 scores) -> g_attn
    attn_kernel<<<dim3(Sdim / QT, Bdim * Hdim), 256, ATTN_SMEM>>>(xh_p, xl_p, attn_p);
    // 2) h = LN(x + attn), qout = cos(h[:, :8]) * cos(theta)
    ln_kernel<<<NTOK, 256>>>(x, attn_p, gamma1, beta1, h_p, qout_p, theta);
    // 3) d_out = h + relu(qout @ w1^T + b1) @ w2t^T + b2  (fully fused, tensor cores)
    ffn_fused<<<dim3(Edim / 128, NTOK / 128), 256, FFN_SMEM>>>(qout_p, w1, b1, w2t_p,
                                                               b2, h_p, out);
    // 4) d_out = LN(d_out), in place
    ln_kernel<<<NTOK, 256>>>(out, nullptr, gamma2, beta2, out, nullptr, nullptr);
}

// round 5
// speedup vs baseline: 1.3199x; 1.3199x over previous
#include <cuda_runtime.h>
#include <cuda_bf16.h>
#include <math.h>
#include <stdint.h>

// Problem dims (fixed by reference)
#define Bdim 4
#define Sdim 2048
#define Edim 1024
#define Hdim 16
#define DKdim 64
#define FFNdim 4096
#define NQdim 8
#define NTOK (Bdim * Sdim)
#define EPSv 1e-5f

// Scratch (alloc-free rule: __device__ globals)
__device__ float g_attn[(size_t)NTOK * Edim];            // 33.5 MB
__device__ float g_h[(size_t)NTOK * Edim];               // 33.5 MB
__device__ float g_qout[NTOK * NQdim];                   // 256 KB
__device__ float g_w2t[(size_t)Edim * FFNdim];           // 16.8 MB (tf32)
__device__ __nv_bfloat16 g_xbh[(size_t)NTOK * Edim];     // 16.8 MB (bf16 hi)
__device__ __nv_bfloat16 g_xbl[(size_t)NTOK * Edim];     // 16.8 MB (bf16 lo)
__device__ __nv_bfloat16 g_xT[(size_t)NTOK * Edim];      // 16.8 MB (V^T, bf16 hi)

// ---------------------------------------------------------------------------
// Helpers
// ---------------------------------------------------------------------------
__device__ __forceinline__ uint32_t smem_u32(const void* p) {
    uint32_t a;
    asm("{ .reg .u64 t; cvta.to.shared.u64 t, %1; cvt.u32.u64 %0, t; }"
        : "=r"(a) : "l"(p));
    return a;
}
__device__ __forceinline__ float cvt_tf32(float v) {
    uint32_t t;
    asm("cvt.rna.tf32.f32 %0, %1;" : "=r"(t) : "f"(v));
    return __uint_as_float(t);
}
__device__ __forceinline__ uint32_t cvt_tf32_u(float v) {
    uint32_t t;
    asm("cvt.rna.tf32.f32 %0, %1;" : "=r"(t) : "f"(v));
    return t;
}
// pack two f32 -> bf16x2 register: lo half = 'lo', hi half = 'hi'
__device__ __forceinline__ uint32_t pack_bf16(float lo, float hi) {
    uint32_t d;
    asm("cvt.rn.bf16x2.f32 %0, %1, %2;" : "=r"(d) : "f"(hi), "f"(lo));
    return d;
}
// round-to-nearest bf16 value as f32
__device__ __forceinline__ float bf16_rn_f(float v) {
    uint32_t u = __float_as_uint(v);
    u = (u + 0x7FFFu + ((u >> 16) & 1u)) & 0xFFFF0000u;
    return __uint_as_float(u);
}
__device__ __forceinline__ void mma_tf32(float c[4], const uint32_t a[4],
                                         const uint32_t b[2]) {
    asm volatile(
        "mma.sync.aligned.m16n8k8.row.col.f32.tf32.tf32.f32 "
        "{%0,%1,%2,%3}, {%4,%5,%6,%7}, {%8,%9}, {%0,%1,%2,%3};"
        : "+f"(c[0]), "+f"(c[1]), "+f"(c[2]), "+f"(c[3])
        : "r"(a[0]), "r"(a[1]), "r"(a[2]), "r"(a[3]), "r"(b[0]), "r"(b[1]));
}
__device__ __forceinline__ void mma_bf16(float c[4], const uint32_t a[4],
                                         const uint32_t b[2]) {
    asm volatile(
        "mma.sync.aligned.m16n8k16.row.col.f32.bf16.bf16.f32 "
        "{%0,%1,%2,%3}, {%4,%5,%6,%7}, {%8,%9}, {%0,%1,%2,%3};"
        : "+f"(c[0]), "+f"(c[1]), "+f"(c[2]), "+f"(c[3])
        : "r"(a[0]), "r"(a[1]), "r"(a[2]), "r"(a[3]), "r"(b[0]), "r"(b[1]));
}
__device__ __forceinline__ void cp16(uint32_t dst, const void* src) {
    asm volatile("cp.async.ca.shared.global [%0], [%1], 16;" :: "r"(dst), "l"(src));
}
__device__ __forceinline__ void cp_commit() {
    asm volatile("cp.async.commit_group;" ::: "memory");
}
template <int N>
__device__ __forceinline__ void cp_wait() {
    asm volatile("cp.async.wait_group %0;" :: "n"(N) : "memory");
}

// ---------------------------------------------------------------------------
// x -> bf16 hi/lo split (elementwise)
// ---------------------------------------------------------------------------
__global__ void __launch_bounds__(256) cvt_split_kernel(const float* __restrict__ x,
                                                        __nv_bfloat16* __restrict__ xbh,
                                                        __nv_bfloat16* __restrict__ xbl) {
    size_t i = ((size_t)blockIdx.x * 256 + threadIdx.x) * 4;
    float4 v = *(const float4*)(x + i);
    float h0 = bf16_rn_f(v.x), h1 = bf16_rn_f(v.y);
    float h2 = bf16_rn_f(v.z), h3 = bf16_rn_f(v.w);
    uint2 ho, lo;
    ho.x = pack_bf16(h0, h1);
    ho.y = pack_bf16(h2, h3);
    lo.x = pack_bf16(v.x - h0, v.y - h1);
    lo.y = pack_bf16(v.z - h2, v.w - h3);
    *(uint2*)(xbh + i) = ho;
    *(uint2*)(xbl + i) = lo;
}

// ---------------------------------------------------------------------------
// Build V^T: xT[(b*H+h)*64 + d][s] = bf16(x[b][s][h*64+d])
// Block: one (b,h) x 64-seq tile. smem transpose.
// ---------------------------------------------------------------------------
__global__ void __launch_bounds__(256) transpose_kernel(const float* __restrict__ x,
                                                        __nv_bfloat16* __restrict__ xT) {
    __shared__ float t[64][65];
    const int bh = blockIdx.y, b = bh >> 4, h = bh & 15;
    const int s0 = blockIdx.x << 6;
    const int tid = threadIdx.x;
#pragma unroll
    for (int i = 0; i < 4; i++) {
        int idx = tid + i * 256;           // 1024 float4 = 64x64
        int r = idx >> 4, c4 = idx & 15;
        float4 v = *(const float4*)(x + ((size_t)(b * Sdim + s0 + r)) * Edim +
                                    h * DKdim + c4 * 4);
        t[r][c4 * 4 + 0] = v.x;
        t[r][c4 * 4 + 1] = v.y;
        t[r][c4 * 4 + 2] = v.z;
        t[r][c4 * 4 + 3] = v.w;
    }
    __syncthreads();
    uint32_t* out = (uint32_t*)(xT + ((size_t)bh * DKdim) * Sdim + s0);
#pragma unroll
    for (int i = 0; i < 8; i++) {
        int idx = tid + i * 256;           // 2048 u32 = 64 dims x 32 pairs
        int d = idx >> 5, k2 = idx & 31;
        out[(size_t)d * (Sdim / 2) + k2] = pack_bf16(t[2 * k2][d], t[2 * k2 + 1][d]);
    }
}

// ---------------------------------------------------------------------------
// w2 -> tf32-rounded copy
// ---------------------------------------------------------------------------
__global__ void __launch_bounds__(256) cvt_w2_kernel(const float* __restrict__ w2,
                                                     float* __restrict__ w2t) {
    size_t i = ((size_t)blockIdx.x * 256 + threadIdx.x) * 4;
    float4 v = *(const float4*)(w2 + i);
    float4 o;
    o.x = cvt_tf32(v.x); o.y = cvt_tf32(v.y);
    o.z = cvt_tf32(v.z); o.w = cvt_tf32(v.w);
    *(float4*)(w2t + i) = o;
}

// ---------------------------------------------------------------------------
// Attention, bf16 mma with register-resident P (FA2 trick).
// Block: one (b,h), 128-query tile, 256 threads = 8 warps, warp tile 16x64.
// GEMM1: 2-way bf16 split (hi*hi + hi*lo + lo*hi). GEMM2: P(hi+lo from regs)
// x V(bf16 hi, pre-transposed). Unnormalized streaming softmax.
// ---------------------------------------------------------------------------
#define KSTR 36                 // smem row stride in u32 (bf16 pairs); 64 dims + pad
#define QT 128
#define KT 64
#define NKT (Sdim / KT)
// u32 words: Qh/Ql 128*36 each, Kh/Kl 2 bufs x 64*36 each, VT 2 bufs x 64*36
#define OFF_QL  (QT * KSTR)                 // 4608
#define OFF_KH  (2 * QT * KSTR)             // 9216
#define OFF_KL  (OFF_KH + 2 * KT * KSTR)    // 13824
#define OFF_VT  (OFF_KL + 2 * KT * KSTR)    // 18432
#define ATTN_WORDS (OFF_VT + 2 * KT * KSTR) // 23040
#define ATTN_SMEM (ATTN_WORDS * 4)          // 92160 B

__global__ void __launch_bounds__(256) attn_kernel(const __nv_bfloat16* __restrict__ xbh,
                                                   const __nv_bfloat16* __restrict__ xbl,
                                                   const __nv_bfloat16* __restrict__ xT,
                                                   float* __restrict__ attn) {
    extern __shared__ uint32_t su[];
    const uint32_t sb = smem_u32(su);

    const int bh = blockIdx.y, b = bh >> 4, h = bh & 15;
    const int q0 = blockIdx.x << 7;
    const int tid = threadIdx.x, lane = tid & 31, w = tid >> 5;
    const int R = w * 16;                    // warp row base (16 rows x 64 cols)
    const int r0 = lane >> 2, c0 = lane & 3;

    const size_t xrow = (size_t)b * Sdim * Edim + h * DKdim;  // elem offset of row 0
    const __nv_bfloat16* qh = xbh + xrow;
    const __nv_bfloat16* ql = xbl + xrow;
    const __nv_bfloat16* vt = xT + (size_t)bh * DKdim * Sdim;

    // ---- load Q tile (hi+lo): 2048 16B chunks ----
#pragma unroll
    for (int i = 0; i < 8; i++) {
        int idx = tid + i * 256;
        int part = idx >> 10, r = (idx >> 3) & 127, ch = idx & 7;
        const __nv_bfloat16* src = (part ? ql : qh) + (size_t)(q0 + r) * Edim + ch * 8;
        cp16(sb + (uint32_t)((part * OFF_QL + r * KSTR + ch * 4) * 4), src);
    }
    cp_commit();

    // ---- K/V tile loader into buffer bf ----
    auto load_kv = [&](int bf, int kt) {
#pragma unroll
        for (int i = 0; i < 4; i++) {        // K hi+lo: 1024 chunks
            int idx = tid + i * 256;
            int part = idx >> 9, r = (idx >> 3) & 63, ch = idx & 7;
            const __nv_bfloat16* src =
                (part ? ql : qh) + (size_t)(kt * KT + r) * Edim + ch * 8;
            uint32_t off = (part ? OFF_KL : OFF_KH) + bf * KT * KSTR + r * KSTR + ch * 4;
            cp16(sb + off * 4, src);
        }
#pragma unroll
        for (int i = 0; i < 2; i++) {        // V^T: 512 chunks
            int idx = tid + i * 256;
            int d = idx >> 3, ch = idx & 7;
            const __nv_bfloat16* src = vt + (size_t)d * Sdim + kt * KT + ch * 8;
            uint32_t off = OFF_VT + bf * KT * KSTR + d * KSTR + ch * 4;
            cp16(sb + off * 4, src);
        }
        cp_commit();
    };
    load_kv(0, 0);

    const uint32_t* Qh = su;
    const uint32_t* Ql = su + OFF_QL;

    float o[8][4] = {};
    float lsum0 = 0.0f, lsum1 = 0.0f;

#pragma unroll 1
    for (int kt = 0; kt < NKT; kt++) {
        const int bf = kt & 1;
        if (kt + 1 < NKT) {
            load_kv(bf ^ 1, kt + 1);
            cp_wait<1>();
        } else {
            cp_wait<0>();
        }
        __syncthreads();

        const uint32_t* Kh = su + OFF_KH + bf * KT * KSTR;
        const uint32_t* Kl = su + OFF_KL + bf * KT * KSTR;
        const uint32_t* VT = su + OFF_VT + bf * KT * KSTR;

        // ---- GEMM1: S = Q K^T, 2-way bf16 split ----
        float s[8][4] = {};
#pragma unroll
        for (int ks = 0; ks < 4; ks++) {
            const int kc = ks * 8 + c0;
            uint32_t ah[4], al[4];
            ah[0] = Qh[(R + r0) * KSTR + kc];
            ah[1] = Qh[(R + r0 + 8) * KSTR + kc];
            ah[2] = Qh[(R + r0) * KSTR + kc + 4];
            ah[3] = Qh[(R + r0 + 8) * KSTR + kc + 4];
            al[0] = Ql[(R + r0) * KSTR + kc];
            al[1] = Ql[(R + r0 + 8) * KSTR + kc];
            al[2] = Ql[(R + r0) * KSTR + kc + 4];
            al[3] = Ql[(R + r0 + 8) * KSTR + kc + 4];
#pragma unroll
            for (int nt = 0; nt < 8; nt++) {
                const int nn = nt * 8 + r0;
                uint32_t bh2[2], bl2[2];
                bh2[0] = Kh[nn * KSTR + kc];
                bh2[1] = Kh[nn * KSTR + kc + 4];
                bl2[0] = Kl[nn * KSTR + kc];
                bl2[1] = Kl[nn * KSTR + kc + 4];
                mma_bf16(s[nt], ah, bh2);
                mma_bf16(s[nt], ah, bl2);
                mma_bf16(s[nt], al, bh2);
            }
        }

        // ---- exp + pack P (hi/lo bf16) in regs + GEMM2 per 16-key chunk ----
#pragma unroll
        for (int j = 0; j < 4; j++) {
            float p[8];
#pragma unroll
            for (int half = 0; half < 2; half++) {
                const int nt = 2 * j + half;
#pragma unroll
                for (int e = 0; e < 4; e++) p[half * 4 + e] = __expf(s[nt][e] * 0.125f);
                lsum0 += p[half * 4 + 0] + p[half * 4 + 1];
                lsum1 += p[half * 4 + 2] + p[half * 4 + 3];
            }
            uint32_t aph[4], apl[4];
            float hv;
            hv = bf16_rn_f(p[0]);
            float l00 = p[0] - hv;
            float h00 = hv;
            hv = bf16_rn_f(p[1]); float l01 = p[1] - hv, h01 = hv;
            hv = bf16_rn_f(p[2]); float l02 = p[2] - hv, h02 = hv;
            hv = bf16_rn_f(p[3]); float l03 = p[3] - hv, h03 = hv;
            hv = bf16_rn_f(p[4]); float l04 = p[4] - hv, h04 = hv;
            hv = bf16_rn_f(p[5]); float l05 = p[5] - hv, h05 = hv;
            hv = bf16_rn_f(p[6]); float l06 = p[6] - hv, h06 = hv;
            hv = bf16_rn_f(p[7]); float l07 = p[7] - hv, h07 = hv;
            aph[0] = pack_bf16(h00, h01);
            aph[1] = pack_bf16(h02, h03);
            aph[2] = pack_bf16(h04, h05);
            aph[3] = pack_bf16(h06, h07);
            apl[0] = pack_bf16(l00, l01);
            apl[1] = pack_bf16(l02, l03);
            apl[2] = pack_bf16(l04, l05);
            apl[3] = pack_bf16(l06, l07);

            const int kc = j * 8 + c0;
#pragma unroll
            for (int nt = 0; nt < 8; nt++) {
                const int nn = nt * 8 + r0;       // dim index
                uint32_t bb[2];
                bb[0] = VT[nn * KSTR + kc];
                bb[1] = VT[nn * KSTR + kc + 4];
                mma_bf16(o[nt], aph, bb);
                mma_bf16(o[nt], apl, bb);
            }
        }
        __syncthreads();   // buffers consumed before next prefetch overwrites
    }

    // ---- normalize + write ----
    lsum0 += __shfl_xor_sync(0xffffffffu, lsum0, 1);
    lsum0 += __shfl_xor_sync(0xffffffffu, lsum0, 2);
    lsum1 += __shfl_xor_sync(0xffffffffu, lsum1, 1);
    lsum1 += __shfl_xor_sync(0xffffffffu, lsum1, 2);
    const float li0 = 1.0f / lsum0, li1 = 1.0f / lsum1;

    float* ob = attn + ((size_t)b * Sdim + q0 + R) * Edim + h * DKdim;
#pragma unroll
    for (int nt = 0; nt < 8; nt++) {
        const int cc = nt * 8 + c0 * 2;
        float2 v0, v1;
        v0.x = o[nt][0] * li0; v0.y = o[nt][1] * li0;
        v1.x = o[nt][2] * li1; v1.y = o[nt][3] * li1;
        *(float2*)(ob + (size_t)r0 * Edim + cc) = v0;
        *(float2*)(ob + (size_t)(r0 + 8) * Edim + cc) = v1;
    }
}

// ---------------------------------------------------------------------------
// Residual + LayerNorm (unchanged)
// ---------------------------------------------------------------------------
__global__ void __launch_bounds__(256) ln_kernel(const float* __restrict__ a,
                                                 const float* __restrict__ resid,
                                                 const float* __restrict__ gamma,
                                                 const float* __restrict__ beta,
                                                 float* __restrict__ out,
                                                 float* __restrict__ qout,
                                                 const float* __restrict__ theta) {
    const int t = blockIdx.x;
    const int tid = threadIdx.x;
    const float* pa = a + (size_t)t * Edim;
    const float* pr = resid ? resid + (size_t)t * Edim : nullptr;

    float v[4];
    float s = 0.0f, s2 = 0.0f;
#pragma unroll
    for (int i = 0; i < 4; i++) {
        int e = tid + i * 256;
        float val = pa[e];
        if (pr) val += pr[e];
        v[i] = val;
        s += val;
        s2 += val * val;
    }
#pragma unroll
    for (int off = 16; off > 0; off >>= 1) {
        s  += __shfl_down_sync(0xffffffffu, s, off);
        s2 += __shfl_down_sync(0xffffffffu, s2, off);
    }
    __shared__ float r1[8], r2[8], stat[2];
    const int warp = tid >> 5, lane = tid & 31;
    if (lane == 0) { r1[warp] = s; r2[warp] = s2; }
    __syncthreads();
    if (tid == 0) {
        float S1 = 0.0f, S2 = 0.0f;
#pragma unroll
        for (int wi = 0; wi < 8; wi++) { S1 += r1[wi]; S2 += r2[wi]; }
        float mu = S1 * (1.0f / Edim);
        float var = S2 * (1.0f / Edim) - mu * mu;
        stat[0] = mu;
        stat[1] = rsqrtf(var + EPSv);
    }
    __syncthreads();
    const float mu = stat[0], rs = stat[1];

    float* po = out + (size_t)t * Edim;
#pragma unroll
    for (int i = 0; i < 4; i++) {
        int e = tid + i * 256;
        po[e] = (v[i] - mu) * rs * gamma[e] + beta[e];
    }
    if (qout != nullptr && tid < NQdim) {
        float hv = (v[0] - mu) * rs * gamma[tid] + beta[tid];
        qout[t * NQdim + tid] = cosf(hv) * cosf(theta[tid]);
    }
}

// ---------------------------------------------------------------------------
// Fused FFN (unchanged from R4): out = h + relu(qout @ w1^T + b1) @ w2t^T + b2
// ---------------------------------------------------------------------------
#define ASTR 68
#define FK 64
#define NFCH (FFNdim / FK)   // 64
#define FFN_SMEM ((QT * ASTR + 2 * QT * ASTR + 2 * FK * 8 + 2 * FK) * 4)  // 108992 B

__global__ void __launch_bounds__(256) ffn_fused(const float* __restrict__ qout,
                                                 const float* __restrict__ w1,
                                                 const float* __restrict__ b1,
                                                 const float* __restrict__ w2t,
                                                 const float* __restrict__ b2,
                                                 const float* __restrict__ hres,
                                                 float* __restrict__ out) {
    extern __shared__ float sm[];
    float* As  = sm;
    float* Bs0 = As + QT * ASTR;
    float* w1s = Bs0 + 2 * QT * ASTR;
    float* b1s = w1s + 2 * FK * 8;

    const uint32_t sB = smem_u32(Bs0), sW1 = smem_u32(w1s), sB1 = smem_u32(b1s);
    const int tid = threadIdx.x, lane = tid & 31, w = tid >> 5;
    const int mw = w >> 1, nw = w & 1;
    const int RM = mw * 32, CN = nw * 64;
    const int r0 = lane >> 2, c0 = lane & 3;
    const int e0 = blockIdx.x * 128;
    const int t0 = blockIdx.y * 128;

    uint32_t aq[2][4];
#pragma unroll
    for (int mt = 0; mt < 2; mt++) {
#pragma unroll
        for (int j = 0; j < 4; j++) {
            int row = t0 + RM + mt * 16 + r0 + (j & 1) * 8;
            int col = c0 + (j >> 1) * 4;
            aq[mt][j] = cvt_tf32_u(qout[row * NQdim + col]);
        }
    }

    auto load_chunk = [&](int ls, int lc) {
        uint32_t Bb = sB + (uint32_t)(ls * QT * ASTR * 4);
#pragma unroll
        for (int i = 0; i < 8; i++) {
            int idx = tid + i * 256;
            int r = idx >> 4, ch = idx & 15;
            cp16(Bb + (uint32_t)(r * ASTR * 4 + ch * 16),
                 w2t + (size_t)(e0 + r) * FFNdim + lc * FK + ch * 4);
        }
        if (tid < 128) {
            int r = tid >> 1, ch = tid & 1;
            cp16(sW1 + (uint32_t)(ls * FK * 8 * 4 + (r * 8 + ch * 4) * 4),
                 w1 + (size_t)(lc * FK + r) * NQdim + ch * 4);
        } else if (tid < 144) {
            int i = tid - 128;
            cp16(sB1 + (uint32_t)(ls * FK * 4 + i * 16), b1 + lc * FK + i * 4);
        }
        cp_commit();
    };
    load_chunk(0, 0);

    float o[2][8][4] = {};

#pragma unroll 1
    for (int kc = 0; kc < NFCH; kc++) {
        const int s = kc & 1;
        if (kc + 1 < NFCH) {
            load_chunk(s ^ 1, kc + 1);
            cp_wait<1>();
        } else {
            cp_wait<0>();
        }
        __syncthreads();

        {
            const float* w1c = w1s + s * FK * 8;
            const float* b1c = b1s + s * FK;
#pragma unroll
            for (int nt2 = 0; nt2 < 4; nt2++) {
                const int f0 = nw * 32 + nt2 * 8;
                uint32_t bw[2];
                bw[0] = cvt_tf32_u(w1c[(f0 + r0) * 8 + c0]);
                bw[1] = cvt_tf32_u(w1c[(f0 + r0) * 8 + c0 + 4]);
                float bv0 = b1c[f0 + c0 * 2], bv1 = b1c[f0 + c0 * 2 + 1];
#pragma unroll
                for (int mt = 0; mt < 2; mt++) {
                    float c4[4] = {0.f, 0.f, 0.f, 0.f};
                    mma_tf32(c4, aq[mt], bw);
                    int row = RM + mt * 16 + r0;
                    float2 v0, v1;
                    v0.x = cvt_tf32(fmaxf(c4[0] + bv0, 0.0f));
                    v0.y = cvt_tf32(fmaxf(c4[1] + bv1, 0.0f));
                    v1.x = cvt_tf32(fmaxf(c4[2] + bv0, 0.0f));
                    v1.y = cvt_tf32(fmaxf(c4[3] + bv1, 0.0f));
                    *(float2*)(As + row * ASTR + f0 + c0 * 2) = v0;
                    *(float2*)(As + (row + 8) * ASTR + f0 + c0 * 2) = v1;
                }
            }
        }
        __syncthreads();

        const float* Bsc = Bs0 + s * QT * ASTR;
#pragma unroll
        for (int ks = 0; ks < 8; ks++) {
            const int kk = ks * 8 + c0;
            uint32_t a[2][4];
#pragma unroll
            for (int mt = 0; mt < 2; mt++) {
                int rr = RM + mt * 16 + r0;
                a[mt][0] = __float_as_uint(As[rr * ASTR + kk]);
                a[mt][1] = __float_as_uint(As[(rr + 8) * ASTR + kk]);
                a[mt][2] = __float_as_uint(As[rr * ASTR + kk + 4]);
                a[mt][3] = __float_as_uint(As[(rr + 8) * ASTR + kk + 4]);
            }
#pragma unroll
            for (int nt = 0; nt < 8; nt++) {
                int nn = CN + nt * 8 + r0;
                uint32_t bb[2];
                bb[0] = __float_as_uint(Bsc[nn * ASTR + kk]);
                bb[1] = __float_as_uint(Bsc[nn * ASTR + kk + 4]);
                mma_tf32(o[0][nt], a[0], bb);
                mma_tf32(o[1][nt], a[1], bb);
            }
        }
        __syncthreads();
    }

#pragma unroll
    for (int mt = 0; mt < 2; mt++)
#pragma unroll
        for (int hh = 0; hh < 2; hh++) {
            int tt = t0 + RM + mt * 16 + r0 + hh * 8;
#pragma unroll
            for (int nt = 0; nt < 8; nt++) {
                int ee = e0 + CN + nt * 8 + c0 * 2;
                float2 hv = *(const float2*)(hres + (size_t)tt * Edim + ee);
                float2 bv = *(const float2*)(b2 + ee);
                float2 ov;
                ov.x = o[mt][nt][hh * 2] + hv.x + bv.x;
                ov.y = o[mt][nt][hh * 2 + 1] + hv.y + bv.y;
                *(float2*)(out + (size_t)tt * Edim + ee) = ov;
            }
        }
}

// ---------------------------------------------------------------------------
extern "C" void kernel_launch(void* const* d_in, const int* in_sizes, int n_in,
                              void* d_out, int out_size) {
    const float* x      = (const float*)d_in[0];
    const float* theta  = (const float*)d_in[1];
    const float* w1     = (const float*)d_in[2];
    const float* b1     = (const float*)d_in[3];
    const float* w2     = (const float*)d_in[4];
    const float* b2     = (const float*)d_in[5];
    const float* gamma1 = (const float*)d_in[6];
    const float* beta1  = (const float*)d_in[7];
    const float* gamma2 = (const float*)d_in[8];
    const float* beta2  = (const float*)d_in[9];
    float* out = (float*)d_out;

    float *attn_p, *h_p, *qout_p, *w2t_p;
    __nv_bfloat16 *xbh_p, *xbl_p, *xT_p;
    cudaGetSymbolAddress((void**)&attn_p, g_attn);
    cudaGetSymbolAddress((void**)&h_p, g_h);
    cudaGetSymbolAddress((void**)&qout_p, g_qout);
    cudaGetSymbolAddress((void**)&w2t_p, g_w2t);
    cudaGetSymbolAddress((void**)&xbh_p, g_xbh);
    cudaGetSymbolAddress((void**)&xbl_p, g_xbl);
    cudaGetSymbolAddress((void**)&xT_p, g_xT);

    cudaFuncSetAttribute(attn_kernel, cudaFuncAttributeMaxDynamicSharedMemorySize,
                         ATTN_SMEM);
    cudaFuncSetAttribute(ffn_fused, cudaFuncAttributeMaxDynamicSharedMemorySize,
                         FFN_SMEM);

    // 0) precision prep
    cvt_w2_kernel<<<(Edim * FFNdim) / 1024, 256>>>(w2, w2t_p);
    cvt_split_kernel<<<((size_t)NTOK * Edim) / 1024, 256>>>(x, xbh_p, xbl_p);
    transpose_kernel<<<dim3(Sdim / 64, Bdim * Hdim), 256>>>(x, xT_p);
    // 1) attention (bf16 mma, register P) -> g_attn
    attn_kernel<<<dim3(Sdim / QT, Bdim * Hdim), 256, ATTN_SMEM>>>(xbh_p, xbl_p, xT_p,
                                                                  attn_p);
    // 2) h = LN(x + attn), qout = cos(h[:, :8]) * cos(theta)
    ln_kernel<<<NTOK, 256>>>(x, attn_p, gamma1, beta1, h_p, qout_p, theta);
    // 3) d_out = h + relu(qout @ w1^T + b1) @ w2t^T + b2
    ffn_fused<<<dim3(Edim / 128, NTOK / 128), 256, FFN_SMEM>>>(qout_p, w1, b1, w2t_p,
                                                               b2, h_p, out);
    // 4) d_out = LN(d_out), in place
    ln_kernel<<<NTOK, 256>>>(out, nullptr, gamma2, beta2, out, nullptr, nullptr);
}

// round 6
// speedup vs baseline: 1.3895x; 1.0527x over previous
#include <cuda_runtime.h>
#include <cuda_bf16.h>
#include <math.h>
#include <stdint.h>

// Problem dims (fixed by reference)
#define Bdim 4
#define Sdim 2048
#define Edim 1024
#define Hdim 16
#define DKdim 64
#define FFNdim 4096
#define NQdim 8
#define NTOK (Bdim * Sdim)
#define EPSv 1e-5f

// Scratch (alloc-free rule: __device__ globals)
__device__ float g_attn[(size_t)NTOK * Edim];            // 33.5 MB
__device__ float g_h[(size_t)NTOK * Edim];               // 33.5 MB
__device__ float g_qout[NTOK * NQdim];                   // 256 KB
__device__ float g_w2t[(size_t)Edim * FFNdim];           // 16.8 MB (tf32)
__device__ __nv_bfloat16 g_xbh[(size_t)NTOK * Edim];     // 16.8 MB (bf16 hi)
__device__ __nv_bfloat16 g_xbl[(size_t)NTOK * Edim];     // 16.8 MB (bf16 lo)
__device__ __nv_bfloat16 g_xT[(size_t)NTOK * Edim];      // 16.8 MB (V^T, bf16 hi)

// ---------------------------------------------------------------------------
// Helpers
// ---------------------------------------------------------------------------
__device__ __forceinline__ uint32_t smem_u32(const void* p) {
    uint32_t a;
    asm("{ .reg .u64 t; cvta.to.shared.u64 t, %1; cvt.u32.u64 %0, t; }"
        : "=r"(a) : "l"(p));
    return a;
}
__device__ __forceinline__ float cvt_tf32(float v) {
    uint32_t t;
    asm("cvt.rna.tf32.f32 %0, %1;" : "=r"(t) : "f"(v));
    return __uint_as_float(t);
}
__device__ __forceinline__ uint32_t cvt_tf32_u(float v) {
    uint32_t t;
    asm("cvt.rna.tf32.f32 %0, %1;" : "=r"(t) : "f"(v));
    return t;
}
__device__ __forceinline__ uint32_t pack_bf16(float lo, float hi) {
    uint32_t d;
    asm("cvt.rn.bf16x2.f32 %0, %1, %2;" : "=r"(d) : "f"(hi), "f"(lo));
    return d;
}
__device__ __forceinline__ float bf16_rn_f(float v) {
    uint32_t u = __float_as_uint(v);
    u = (u + 0x7FFFu + ((u >> 16) & 1u)) & 0xFFFF0000u;
    return __uint_as_float(u);
}
__device__ __forceinline__ void mma_tf32(float c[4], const uint32_t a[4],
                                         const uint32_t b[2]) {
    asm volatile(
        "mma.sync.aligned.m16n8k8.row.col.f32.tf32.tf32.f32 "
        "{%0,%1,%2,%3}, {%4,%5,%6,%7}, {%8,%9}, {%0,%1,%2,%3};"
        : "+f"(c[0]), "+f"(c[1]), "+f"(c[2]), "+f"(c[3])
        : "r"(a[0]), "r"(a[1]), "r"(a[2]), "r"(a[3]), "r"(b[0]), "r"(b[1]));
}
__device__ __forceinline__ void mma_bf16(float c[4], const uint32_t a[4],
                                         const uint32_t b[2]) {
    asm volatile(
        "mma.sync.aligned.m16n8k16.row.col.f32.bf16.bf16.f32 "
        "{%0,%1,%2,%3}, {%4,%5,%6,%7}, {%8,%9}, {%0,%1,%2,%3};"
        : "+f"(c[0]), "+f"(c[1]), "+f"(c[2]), "+f"(c[3])
        : "r"(a[0]), "r"(a[1]), "r"(a[2]), "r"(a[3]), "r"(b[0]), "r"(b[1]));
}
// ldmatrix: 4 8x8-b16 tiles; lane i supplies row address of tile i/8
__device__ __forceinline__ void ldm_x4(uint32_t r[4], uint32_t a) {
    asm volatile("ldmatrix.sync.aligned.m8n8.x4.shared.b16 {%0,%1,%2,%3}, [%4];"
                 : "=r"(r[0]), "=r"(r[1]), "=r"(r[2]), "=r"(r[3]) : "r"(a));
}
__device__ __forceinline__ void cp16(uint32_t dst, const void* src) {
    asm volatile("cp.async.ca.shared.global [%0], [%1], 16;" :: "r"(dst), "l"(src));
}
__device__ __forceinline__ void cp_commit() {
    asm volatile("cp.async.commit_group;" ::: "memory");
}
template <int N>
__device__ __forceinline__ void cp_wait() {
    asm volatile("cp.async.wait_group %0;" :: "n"(N) : "memory");
}

// ---------------------------------------------------------------------------
// x -> bf16 hi/lo split (elementwise)
// ---------------------------------------------------------------------------
__global__ void __launch_bounds__(256) cvt_split_kernel(const float* __restrict__ x,
                                                        __nv_bfloat16* __restrict__ xbh,
                                                        __nv_bfloat16* __restrict__ xbl) {
    size_t i = ((size_t)blockIdx.x * 256 + threadIdx.x) * 4;
    float4 v = *(const float4*)(x + i);
    float h0 = bf16_rn_f(v.x), h1 = bf16_rn_f(v.y);
    float h2 = bf16_rn_f(v.z), h3 = bf16_rn_f(v.w);
    uint2 ho, lo;
    ho.x = pack_bf16(h0, h1);
    ho.y = pack_bf16(h2, h3);
    lo.x = pack_bf16(v.x - h0, v.y - h1);
    lo.y = pack_bf16(v.z - h2, v.w - h3);
    *(uint2*)(xbh + i) = ho;
    *(uint2*)(xbl + i) = lo;
}

// ---------------------------------------------------------------------------
// Build V^T: xT[(b*H+h)*64 + d][s] = bf16(x[b][s][h*64+d])
// ---------------------------------------------------------------------------
__global__ void __launch_bounds__(256) transpose_kernel(const float* __restrict__ x,
                                                        __nv_bfloat16* __restrict__ xT) {
    __shared__ float t[64][65];
    const int bh = blockIdx.y, b = bh >> 4, h = bh & 15;
    const int s0 = blockIdx.x << 6;
    const int tid = threadIdx.x;
#pragma unroll
    for (int i = 0; i < 4; i++) {
        int idx = tid + i * 256;
        int r = idx >> 4, c4 = idx & 15;
        float4 v = *(const float4*)(x + ((size_t)(b * Sdim + s0 + r)) * Edim +
                                    h * DKdim + c4 * 4);
        t[r][c4 * 4 + 0] = v.x;
        t[r][c4 * 4 + 1] = v.y;
        t[r][c4 * 4 + 2] = v.z;
        t[r][c4 * 4 + 3] = v.w;
    }
    __syncthreads();
    uint32_t* out = (uint32_t*)(xT + ((size_t)bh * DKdim) * Sdim + s0);
#pragma unroll
    for (int i = 0; i < 8; i++) {
        int idx = tid + i * 256;
        int d = idx >> 5, k2 = idx & 31;
        out[(size_t)d * (Sdim / 2) + k2] = pack_bf16(t[2 * k2][d], t[2 * k2 + 1][d]);
    }
}

// ---------------------------------------------------------------------------
// w2 -> tf32-rounded copy
// ---------------------------------------------------------------------------
__global__ void __launch_bounds__(256) cvt_w2_kernel(const float* __restrict__ w2,
                                                     float* __restrict__ w2t) {
    size_t i = ((size_t)blockIdx.x * 256 + threadIdx.x) * 4;
    float4 v = *(const float4*)(w2 + i);
    float4 o;
    o.x = cvt_tf32(v.x); o.y = cvt_tf32(v.y);
    o.z = cvt_tf32(v.z); o.w = cvt_tf32(v.w);
    *(float4*)(w2t + i) = o;
}

// ---------------------------------------------------------------------------
// Attention, bf16 mma + ldmatrix, register-resident P.
// Block: one (b,h), 128-query tile, 256 threads = 8 warps, warp tile 16x64.
// ---------------------------------------------------------------------------
#define KSTR 36
#define QT 128
#define KT 64
#define NKT (Sdim / KT)
#define OFF_QL  (QT * KSTR)
#define OFF_KH  (2 * QT * KSTR)
#define OFF_KL  (OFF_KH + 2 * KT * KSTR)
#define OFF_VT  (OFF_KL + 2 * KT * KSTR)
#define ATTN_WORDS (OFF_VT + 2 * KT * KSTR)
#define ATTN_SMEM (ATTN_WORDS * 4)          // 92160 B

__global__ void __launch_bounds__(256) attn_kernel(const __nv_bfloat16* __restrict__ xbh,
                                                   const __nv_bfloat16* __restrict__ xbl,
                                                   const __nv_bfloat16* __restrict__ xT,
                                                   float* __restrict__ attn) {
    extern __shared__ uint32_t su[];
    const uint32_t sb = smem_u32(su);

    const int bh = blockIdx.y, b = bh >> 4, h = bh & 15;
    const int q0 = blockIdx.x << 7;
    const int tid = threadIdx.x, lane = tid & 31, w = tid >> 5;
    const int R = w * 16;
    const int r0 = lane >> 2, c0 = lane & 3;

    // per-lane ldmatrix row addresses (u32-word offsets)
    // A tiles: t0=(r,k0) t1=(r+8,k0) t2=(r,k4) t3=(r+8,k4)
    const uint32_t laneA =
        (uint32_t)((R + (lane & 7) + 8 * ((lane >> 3) & 1)) * KSTR +
                   4 * ((lane >> 4) & 1));
    // B tiles: t0=(n,k0) t1=(n,k4) t2=(n+8,k0) t3=(n+8,k4)
    const uint32_t laneB =
        (uint32_t)(((lane & 7) + 8 * ((lane >> 4) & 1)) * KSTR +
                   4 * ((lane >> 3) & 1));

    const size_t xrow = (size_t)b * Sdim * Edim + h * DKdim;
    const __nv_bfloat16* qh = xbh + xrow;
    const __nv_bfloat16* ql = xbl + xrow;
    const __nv_bfloat16* vt = xT + (size_t)bh * DKdim * Sdim;

    // ---- load Q tile (hi+lo) ----
#pragma unroll
    for (int i = 0; i < 8; i++) {
        int idx = tid + i * 256;
        int part = idx >> 10, r = (idx >> 3) & 127, ch = idx & 7;
        const __nv_bfloat16* src = (part ? ql : qh) + (size_t)(q0 + r) * Edim + ch * 8;
        cp16(sb + (uint32_t)((part * OFF_QL + r * KSTR + ch * 4) * 4), src);
    }
    cp_commit();

    auto load_kv = [&](int bf, int kt) {
#pragma unroll
        for (int i = 0; i < 4; i++) {
            int idx = tid + i * 256;
            int part = idx >> 9, r = (idx >> 3) & 63, ch = idx & 7;
            const __nv_bfloat16* src =
                (part ? ql : qh) + (size_t)(kt * KT + r) * Edim + ch * 8;
            uint32_t off = (part ? OFF_KL : OFF_KH) + bf * KT * KSTR + r * KSTR + ch * 4;
            cp16(sb + off * 4, src);
        }
#pragma unroll
        for (int i = 0; i < 2; i++) {
            int idx = tid + i * 256;
            int d = idx >> 3, ch = idx & 7;
            const __nv_bfloat16* src = vt + (size_t)d * Sdim + kt * KT + ch * 8;
            uint32_t off = OFF_VT + bf * KT * KSTR + d * KSTR + ch * 4;
            cp16(sb + off * 4, src);
        }
        cp_commit();
    };
    load_kv(0, 0);

    const uint32_t qh_a = sb + 4 * laneA;
    const uint32_t ql_a = sb + 4 * (OFF_QL + laneA);

    float o[8][4] = {};
    float lsum0 = 0.0f, lsum1 = 0.0f;

#pragma unroll 1
    for (int kt = 0; kt < NKT; kt++) {
        const int bf = kt & 1;
        if (kt + 1 < NKT) {
            load_kv(bf ^ 1, kt + 1);
            cp_wait<1>();
        } else {
            cp_wait<0>();
        }
        __syncthreads();

        const uint32_t kh_a = sb + 4 * (OFF_KH + bf * KT * KSTR + laneB);
        const uint32_t kl_a = sb + 4 * (OFF_KL + bf * KT * KSTR + laneB);
        const uint32_t vt_a = sb + 4 * (OFF_VT + bf * KT * KSTR + laneB);

        // ---- GEMM1: S = Q K^T, 2-way bf16 split, ldmatrix operands ----
        float s[8][4] = {};
#pragma unroll
        for (int ks = 0; ks < 4; ks++) {
            const uint32_t kb4 = (uint32_t)(ks * 8) * 4;
            uint32_t ah[4], al[4];
            ldm_x4(ah, qh_a + kb4);
            ldm_x4(al, ql_a + kb4);
#pragma unroll
            for (int ntp = 0; ntp < 4; ntp++) {
                const uint32_t boff = (uint32_t)(ntp * 16 * KSTR) * 4 + kb4;
                uint32_t bh4[4], bl4[4];
                ldm_x4(bh4, kh_a + boff);
                ldm_x4(bl4, kl_a + boff);
                mma_bf16(s[2 * ntp], ah, bh4);
                mma_bf16(s[2 * ntp], ah, bl4);
                mma_bf16(s[2 * ntp], al, bh4);
                mma_bf16(s[2 * ntp + 1], ah, bh4 + 2);
                mma_bf16(s[2 * ntp + 1], ah, bl4 + 2);
                mma_bf16(s[2 * ntp + 1], al, bh4 + 2);
            }
        }

        // ---- exp + pack P (hi/lo) in regs + GEMM2 per 16-key chunk ----
#pragma unroll
        for (int j = 0; j < 4; j++) {
            float p[8];
#pragma unroll
            for (int half = 0; half < 2; half++) {
                const int nt = 2 * j + half;
#pragma unroll
                for (int e = 0; e < 4; e++) p[half * 4 + e] = __expf(s[nt][e] * 0.125f);
                lsum0 += p[half * 4 + 0] + p[half * 4 + 1];
                lsum1 += p[half * 4 + 2] + p[half * 4 + 3];
            }
            uint32_t aph[4], apl[4];
            float hv;
            hv = bf16_rn_f(p[0]); float l00 = p[0] - hv, h00 = hv;
            hv = bf16_rn_f(p[1]); float l01 = p[1] - hv, h01 = hv;
            hv = bf16_rn_f(p[2]); float l02 = p[2] - hv, h02 = hv;
            hv = bf16_rn_f(p[3]); float l03 = p[3] - hv, h03 = hv;
            hv = bf16_rn_f(p[4]); float l04 = p[4] - hv, h04 = hv;
            hv = bf16_rn_f(p[5]); float l05 = p[5] - hv, h05 = hv;
            hv = bf16_rn_f(p[6]); float l06 = p[6] - hv, h06 = hv;
            hv = bf16_rn_f(p[7]); float l07 = p[7] - hv, h07 = hv;
            aph[0] = pack_bf16(h00, h01);
            aph[1] = pack_bf16(h02, h03);
            aph[2] = pack_bf16(h04, h05);
            aph[3] = pack_bf16(h06, h07);
            apl[0] = pack_bf16(l00, l01);
            apl[1] = pack_bf16(l02, l03);
            apl[2] = pack_bf16(l04, l05);
            apl[3] = pack_bf16(l06, l07);

            const uint32_t kb4 = (uint32_t)(j * 8) * 4;
#pragma unroll
            for (int ntp = 0; ntp < 4; ntp++) {
                uint32_t bv4[4];
                ldm_x4(bv4, vt_a + (uint32_t)(ntp * 16 * KSTR) * 4 + kb4);
                mma_bf16(o[2 * ntp], aph, bv4);
                mma_bf16(o[2 * ntp], apl, bv4);
                mma_bf16(o[2 * ntp + 1], aph, bv4 + 2);
                mma_bf16(o[2 * ntp + 1], apl, bv4 + 2);
            }
        }
        __syncthreads();
    }

    // ---- normalize + write ----
    lsum0 += __shfl_xor_sync(0xffffffffu, lsum0, 1);
    lsum0 += __shfl_xor_sync(0xffffffffu, lsum0, 2);
    lsum1 += __shfl_xor_sync(0xffffffffu, lsum1, 1);
    lsum1 += __shfl_xor_sync(0xffffffffu, lsum1, 2);
    const float li0 = 1.0f / lsum0, li1 = 1.0f / lsum1;

    float* ob = attn + ((size_t)b * Sdim + q0 + R) * Edim + h * DKdim;
#pragma unroll
    for (int nt = 0; nt < 8; nt++) {
        const int cc = nt * 8 + c0 * 2;
        float2 v0, v1;
        v0.x = o[nt][0] * li0; v0.y = o[nt][1] * li0;
        v1.x = o[nt][2] * li1; v1.y = o[nt][3] * li1;
        *(float2*)(ob + (size_t)r0 * Edim + cc) = v0;
        *(float2*)(ob + (size_t)(r0 + 8) * Edim + cc) = v1;
    }
}

// ---------------------------------------------------------------------------
// Residual + LayerNorm (unchanged)
// ---------------------------------------------------------------------------
__global__ void __launch_bounds__(256) ln_kernel(const float* __restrict__ a,
                                                 const float* __restrict__ resid,
                                                 const float* __restrict__ gamma,
                                                 const float* __restrict__ beta,
                                                 float* __restrict__ out,
                                                 float* __restrict__ qout,
                                                 const float* __restrict__ theta) {
    const int t = blockIdx.x;
    const int tid = threadIdx.x;
    const float* pa = a + (size_t)t * Edim;
    const float* pr = resid ? resid + (size_t)t * Edim : nullptr;

    float v[4];
    float s = 0.0f, s2 = 0.0f;
#pragma unroll
    for (int i = 0; i < 4; i++) {
        int e = tid + i * 256;
        float val = pa[e];
        if (pr) val += pr[e];
        v[i] = val;
        s += val;
        s2 += val * val;
    }
#pragma unroll
    for (int off = 16; off > 0; off >>= 1) {
        s  += __shfl_down_sync(0xffffffffu, s, off);
        s2 += __shfl_down_sync(0xffffffffu, s2, off);
    }
    __shared__ float r1[8], r2[8], stat[2];
    const int warp = tid >> 5, lane = tid & 31;
    if (lane == 0) { r1[warp] = s; r2[warp] = s2; }
    __syncthreads();
    if (tid == 0) {
        float S1 = 0.0f, S2 = 0.0f;
#pragma unroll
        for (int wi = 0; wi < 8; wi++) { S1 += r1[wi]; S2 += r2[wi]; }
        float mu = S1 * (1.0f / Edim);
        float var = S2 * (1.0f / Edim) - mu * mu;
        stat[0] = mu;
        stat[1] = rsqrtf(var + EPSv);
    }
    __syncthreads();
    const float mu = stat[0], rs = stat[1];

    float* po = out + (size_t)t * Edim;
#pragma unroll
    for (int i = 0; i < 4; i++) {
        int e = tid + i * 256;
        po[e] = (v[i] - mu) * rs * gamma[e] + beta[e];
    }
    if (qout != nullptr && tid < NQdim) {
        float hv = (v[0] - mu) * rs * gamma[tid] + beta[tid];
        qout[t * NQdim + tid] = cosf(hv) * cosf(theta[tid]);
    }
}

// ---------------------------------------------------------------------------
// Fused FFN: out = h + relu(qout @ w1^T + b1) @ w2t^T + b2  (tf32 + ldmatrix)
// ---------------------------------------------------------------------------
#define ASTR 68
#define FK 64
#define NFCH (FFNdim / FK)   // 64
#define FFN_SMEM ((QT * ASTR + 2 * QT * ASTR + 2 * FK * 8 + 2 * FK) * 4)  // 108992 B

__global__ void __launch_bounds__(256) ffn_fused(const float* __restrict__ qout,
                                                 const float* __restrict__ w1,
                                                 const float* __restrict__ b1,
                                                 const float* __restrict__ w2t,
                                                 const float* __restrict__ b2,
                                                 const float* __restrict__ hres,
                                                 float* __restrict__ out) {
    extern __shared__ float sm[];
    float* As  = sm;
    float* Bs0 = As + QT * ASTR;
    float* w1s = Bs0 + 2 * QT * ASTR;
    float* b1s = w1s + 2 * FK * 8;

    const uint32_t sA = smem_u32(As);
    const uint32_t sB = smem_u32(Bs0), sW1 = smem_u32(w1s), sB1 = smem_u32(b1s);
    const int tid = threadIdx.x, lane = tid & 31, w = tid >> 5;
    const int mw = w >> 1, nw = w & 1;
    const int RM = mw * 32, CN = nw * 64;
    const int r0 = lane >> 2, c0 = lane & 3;
    const int e0 = blockIdx.x * 128;
    const int t0 = blockIdx.y * 128;

    // per-lane ldmatrix row offsets (float-word offsets, tf32 = 4 floats/16B)
    const uint32_t laneAf =
        (uint32_t)(((lane & 7) + 8 * ((lane >> 3) & 1)) * ASTR + 4 * ((lane >> 4) & 1));
    const uint32_t laneBf =
        (uint32_t)(((lane & 7) + 8 * ((lane >> 4) & 1)) * ASTR + 4 * ((lane >> 3) & 1));

    uint32_t aq[2][4];
#pragma unroll
    for (int mt = 0; mt < 2; mt++) {
#pragma unroll
        for (int j = 0; j < 4; j++) {
            int row = t0 + RM + mt * 16 + r0 + (j & 1) * 8;
            int col = c0 + (j >> 1) * 4;
            aq[mt][j] = cvt_tf32_u(qout[row * NQdim + col]);
        }
    }

    auto load_chunk = [&](int ls, int lc) {
        uint32_t Bb = sB + (uint32_t)(ls * QT * ASTR * 4);
#pragma unroll
        for (int i = 0; i < 8; i++) {
            int idx = tid + i * 256;
            int r = idx >> 4, ch = idx & 15;
            cp16(Bb + (uint32_t)(r * ASTR * 4 + ch * 16),
                 w2t + (size_t)(e0 + r) * FFNdim + lc * FK + ch * 4);
        }
        if (tid < 128) {
            int r = tid >> 1, ch = tid & 1;
            cp16(sW1 + (uint32_t)(ls * FK * 8 * 4 + (r * 8 + ch * 4) * 4),
                 w1 + (size_t)(lc * FK + r) * NQdim + ch * 4);
        } else if (tid < 144) {
            int i = tid - 128;
            cp16(sB1 + (uint32_t)(ls * FK * 4 + i * 16), b1 + lc * FK + i * 4);
        }
        cp_commit();
    };
    load_chunk(0, 0);

    float o[2][8][4] = {};

#pragma unroll 1
    for (int kc = 0; kc < NFCH; kc++) {
        const int s = kc & 1;
        if (kc + 1 < NFCH) {
            load_chunk(s ^ 1, kc + 1);
            cp_wait<1>();
        } else {
            cp_wait<0>();
        }
        __syncthreads();

        // ---- build A tile: hid = relu(qout @ w1c^T + b1c), tf32 ----
        {
            const float* w1c = w1s + s * FK * 8;
            const float* b1c = b1s + s * FK;
#pragma unroll
            for (int nt2 = 0; nt2 < 4; nt2++) {
                const int f0 = nw * 32 + nt2 * 8;
                uint32_t bw[2];
                bw[0] = cvt_tf32_u(w1c[(f0 + r0) * 8 + c0]);
                bw[1] = cvt_tf32_u(w1c[(f0 + r0) * 8 + c0 + 4]);
                float bv0 = b1c[f0 + c0 * 2], bv1 = b1c[f0 + c0 * 2 + 1];
#pragma unroll
                for (int mt = 0; mt < 2; mt++) {
                    float c4[4] = {0.f, 0.f, 0.f, 0.f};
                    mma_tf32(c4, aq[mt], bw);
                    int row = RM + mt * 16 + r0;
                    float2 v0, v1;
                    v0.x = cvt_tf32(fmaxf(c4[0] + bv0, 0.0f));
                    v0.y = cvt_tf32(fmaxf(c4[1] + bv1, 0.0f));
                    v1.x = cvt_tf32(fmaxf(c4[2] + bv0, 0.0f));
                    v1.y = cvt_tf32(fmaxf(c4[3] + bv1, 0.0f));
                    *(float2*)(As + row * ASTR + f0 + c0 * 2) = v0;
                    *(float2*)(As + (row + 8) * ASTR + f0 + c0 * 2) = v1;
                }
            }
        }
        __syncthreads();

        // ---- GEMM2 chunk with ldmatrix operands ----
        const uint32_t a_base = sA + 4 * ((uint32_t)RM * ASTR + laneAf);
        const uint32_t b_base = sB + (uint32_t)(s * QT * ASTR * 4) +
                                4 * ((uint32_t)CN * ASTR + laneBf);
#pragma unroll
        for (int ks = 0; ks < 8; ks++) {
            const uint32_t kb4 = (uint32_t)(ks * 8) * 4;
            uint32_t a0[4], a1[4];
            ldm_x4(a0, a_base + kb4);
            ldm_x4(a1, a_base + (uint32_t)(16 * ASTR) * 4 + kb4);
#pragma unroll
            for (int ntp = 0; ntp < 4; ntp++) {
                uint32_t b4[4];
                ldm_x4(b4, b_base + (uint32_t)(ntp * 16 * ASTR) * 4 + kb4);
                mma_tf32(o[0][2 * ntp], a0, b4);
                mma_tf32(o[1][2 * ntp], a1, b4);
                mma_tf32(o[0][2 * ntp + 1], a0, b4 + 2);
                mma_tf32(o[1][2 * ntp + 1], a1, b4 + 2);
            }
        }
        __syncthreads();
    }

    // Epilogue: + b2 + residual h
#pragma unroll
    for (int mt = 0; mt < 2; mt++)
#pragma unroll
        for (int hh = 0; hh < 2; hh++) {
            int tt = t0 + RM + mt * 16 + r0 + hh * 8;
#pragma unroll
            for (int nt = 0; nt < 8; nt++) {
                int ee = e0 + CN + nt * 8 + c0 * 2;
                float2 hv = *(const float2*)(hres + (size_t)tt * Edim + ee);
                float2 bv = *(const float2*)(b2 + ee);
                float2 ov;
                ov.x = o[mt][nt][hh * 2] + hv.x + bv.x;
                ov.y = o[mt][nt][hh * 2 + 1] + hv.y + bv.y;
                *(float2*)(out + (size_t)tt * Edim + ee) = ov;
            }
        }
}

// ---------------------------------------------------------------------------
extern "C" void kernel_launch(void* const* d_in, const int* in_sizes, int n_in,
                              void* d_out, int out_size) {
    const float* x      = (const float*)d_in[0];
    const float* theta  = (const float*)d_in[1];
    const float* w1     = (const float*)d_in[2];
    const float* b1     = (const float*)d_in[3];
    const float* w2     = (const float*)d_in[4];
    const float* b2     = (const float*)d_in[5];
    const float* gamma1 = (const float*)d_in[6];
    const float* beta1  = (const float*)d_in[7];
    const float* gamma2 = (const float*)d_in[8];
    const float* beta2  = (const float*)d_in[9];
    float* out = (float*)d_out;

    float *attn_p, *h_p, *qout_p, *w2t_p;
    __nv_bfloat16 *xbh_p, *xbl_p, *xT_p;
    cudaGetSymbolAddress((void**)&attn_p, g_attn);
    cudaGetSymbolAddress((void**)&h_p, g_h);
    cudaGetSymbolAddress((void**)&qout_p, g_qout);
    cudaGetSymbolAddress((void**)&w2t_p, g_w2t);
    cudaGetSymbolAddress((void**)&xbh_p, g_xbh);
    cudaGetSymbolAddress((void**)&xbl_p, g_xbl);
    cudaGetSymbolAddress((void**)&xT_p, g_xT);

    cudaFuncSetAttribute(attn_kernel, cudaFuncAttributeMaxDynamicSharedMemorySize,
                         ATTN_SMEM);
    cudaFuncSetAttribute(ffn_fused, cudaFuncAttributeMaxDynamicSharedMemorySize,
                         FFN_SMEM);

    // 0) precision prep
    cvt_w2_kernel<<<(Edim * FFNdim) / 1024, 256>>>(w2, w2t_p);
    cvt_split_kernel<<<((size_t)NTOK * Edim) / 1024, 256>>>(x, xbh_p, xbl_p);
    transpose_kernel<<<dim3(Sdim / 64, Bdim * Hdim), 256>>>(x, xT_p);
    // 1) attention (bf16 mma + ldmatrix, register P) -> g_attn
    attn_kernel<<<dim3(Sdim / QT, Bdim * Hdim), 256, ATTN_SMEM>>>(xbh_p, xbl_p, xT_p,
                                                                  attn_p);
    // 2) h = LN(x + attn), qout = cos(h[:, :8]) * cos(theta)
    ln_kernel<<<NTOK, 256>>>(x, attn_p, gamma1, beta1, h_p, qout_p, theta);
    // 3) d_out = h + relu(qout @ w1^T + b1) @ w2t^T + b2
    ffn_fused<<<dim3(Edim / 128, NTOK / 128), 256, FFN_SMEM>>>(qout_p, w1, b1, w2t_p,
                                                               b2, h_p, out);
    // 4) d_out = LN(d_out), in place
    ln_kernel<<<NTOK, 256>>>(out, nullptr, gamma2, beta2, out, nullptr, nullptr);
}